// round 2
// baseline (speedup 1.0000x reference)
#include <cuda_runtime.h>

// Problem constants
#define T_STEPS 4
#define BATCH   32
#define CH      384
#define HW      196
#define HEADS   8
#define DH      48
#define CHW     (CH*HW)          // 75264
#define BCHW    (BATCH*CHW)      // 2408448
#define TOTAL   (T_STEPS*BCHW)   // 9633792
#define NTOT    (T_STEPS*BATCH*HW) // 25088  (= 196 * 128 exactly)

// Scratch (static device globals -- allocation-guard safe)
__device__ float g_qbn[TOTAL];
__device__ float g_kbn[TOTAL];
__device__ float g_y[TOTAL];
__device__ float g_zbn[TOTAL];

// ---------------------------------------------------------------------------
// SGEMM 128x128x8, 256 threads, 8x8 microtile (2x2 of 4x4 blocks), fused BN.
// Columns are the flattened (t,b,hw) dim: col n -> tb = n/196, hw = n%196.
// X element (c, n) lives at X[tb*CHW + c*HW + hw]; output at the same column
// offset + o*HW.  All dims divide the tiles exactly: no masking anywhere.
// ---------------------------------------------------------------------------
__device__ __forceinline__ void gemm_bn_body(
    const float* __restrict__ X, const float* __restrict__ W,
    const float* __restrict__ gamma, const float* __restrict__ beta,
    const float* __restrict__ mean,  const float* __restrict__ var,
    const float* __restrict__ bias,  float* __restrict__ out)
{
    __shared__ float As[8][128];   // [k][m]
    __shared__ float Bs[8][128];   // [k][n]
    __shared__ int   colOff[128];

    const int tid   = threadIdx.x;
    const int mbase = blockIdx.y * 128;
    const int nbase = blockIdx.x * 128;

    if (tid < 128) {
        int n  = nbase + tid;
        int tb = n / HW;
        int hw = n - tb * HW;
        colOff[tid] = tb * CHW + hw;
    }
    __syncthreads();

    const int tx = tid & 15;     // n direction (16)
    const int ty = tid >> 4;     // m direction (16)

    // load mapping
    const int a_row = tid >> 1;        // 0..127
    const int a_col = (tid & 1) * 4;   // 0 or 4
    const int b_k   = tid >> 5;        // 0..7
    const int b_n   = (tid & 31) * 4;  // 0..124

    const int bo0 = colOff[b_n + 0];
    const int bo1 = colOff[b_n + 1];
    const int bo2 = colOff[b_n + 2];
    const int bo3 = colOff[b_n + 3];

    float acc[8][8];
#pragma unroll
    for (int i = 0; i < 8; i++)
#pragma unroll
        for (int j = 0; j < 8; j++) acc[i][j] = 0.f;

    for (int k0 = 0; k0 < CH; k0 += 8) {
        // stage global -> regs
        float4 av = *reinterpret_cast<const float4*>(&W[(mbase + a_row) * CH + k0 + a_col]);
        const int krow = (k0 + b_k) * HW;
        float b0v = X[bo0 + krow];
        float b1v = X[bo1 + krow];
        float b2v = X[bo2 + krow];
        float b3v = X[bo3 + krow];

        __syncthreads();   // previous iteration's smem reads done
        As[a_col + 0][a_row] = av.x;
        As[a_col + 1][a_row] = av.y;
        As[a_col + 2][a_row] = av.z;
        As[a_col + 3][a_row] = av.w;
        *reinterpret_cast<float4*>(&Bs[b_k][b_n]) = make_float4(b0v, b1v, b2v, b3v);
        __syncthreads();

#pragma unroll
        for (int k = 0; k < 8; k++) {
            float4 A0 = *reinterpret_cast<const float4*>(&As[k][ty * 4]);
            float4 A1 = *reinterpret_cast<const float4*>(&As[k][64 + ty * 4]);
            float4 B0 = *reinterpret_cast<const float4*>(&Bs[k][tx * 4]);
            float4 B1 = *reinterpret_cast<const float4*>(&Bs[k][64 + tx * 4]);
            float ar[8] = {A0.x, A0.y, A0.z, A0.w, A1.x, A1.y, A1.z, A1.w};
            float br[8] = {B0.x, B0.y, B0.z, B0.w, B1.x, B1.y, B1.z, B1.w};
#pragma unroll
            for (int i = 0; i < 8; i++)
#pragma unroll
                for (int j = 0; j < 8; j++)
                    acc[i][j] = fmaf(ar[i], br[j], acc[i][j]);
        }
    }

    // BN (+optional conv bias) epilogue, matching reference op order exactly
#pragma unroll
    for (int i = 0; i < 8; i++) {
        int m = (i < 4) ? (ty * 4 + i) : (64 + ty * 4 + (i - 4));
        int o = mbase + m;
        float inv = gamma[o] / sqrtf(var[o] + 1e-5f);
        float sh  = beta[o] - mean[o] * inv;
        float bv  = bias ? bias[o] : 0.f;
#pragma unroll
        for (int j = 0; j < 8; j++) {
            int n = (j < 4) ? (tx * 4 + j) : (64 + tx * 4 + (j - 4));
            float v = acc[i][j] + bv;
            out[colOff[n] + o * HW] = v * inv + sh;
        }
    }
}

__global__ void __launch_bounds__(256) gemm_q_kernel(
    const float* __restrict__ X, const float* __restrict__ W,
    const float* __restrict__ g, const float* __restrict__ b,
    const float* __restrict__ m, const float* __restrict__ v)
{
    gemm_bn_body(X, W, g, b, m, v, nullptr, g_qbn);
}

__global__ void __launch_bounds__(256) gemm_k_kernel(
    const float* __restrict__ X, const float* __restrict__ W,
    const float* __restrict__ g, const float* __restrict__ b,
    const float* __restrict__ m, const float* __restrict__ v)
{
    gemm_bn_body(X, W, g, b, m, v, nullptr, g_kbn);
}

__global__ void __launch_bounds__(256) gemm_proj_kernel(
    const float* __restrict__ W,
    const float* __restrict__ g, const float* __restrict__ b,
    const float* __restrict__ m, const float* __restrict__ v,
    const float* __restrict__ bias)
{
    gemm_bn_body(g_y, W, g, b, m, v, bias, g_zbn);
}

// ---------------------------------------------------------------------------
// LIF on q and k (per channel, over T), per-head sum-pool, attn LIF (vth=0.5),
// gate k spikes -> binary y.  One CTA per (b, head); one thread per hw.
// ---------------------------------------------------------------------------
__global__ void lif_attn_kernel()
{
    int bh   = blockIdx.x;
    int b    = bh >> 3;
    int head = bh & 7;
    int hw   = threadIdx.x;
    if (hw >= HW) return;

    int cbase = head * DH;
    int base0 = b * CHW + cbase * HW + hw;

    float qs[4] = {0.f, 0.f, 0.f, 0.f};
    unsigned long long kb[4] = {0ull, 0ull, 0ull, 0ull};

    for (int d = 0; d < DH; d++) {
        int idx = base0 + d * HW;
        float vq = 0.f, vk = 0.f;
#pragma unroll
        for (int t = 0; t < 4; t++) {
            float xq = g_qbn[idx + t * BCHW];
            float xk = g_kbn[idx + t * BCHW];
            float hq = vq + (xq - vq) * 0.5f;   // tau = 2
            float hk = vk + (xk - vk) * 0.5f;
            bool sq = (hq - 1.0f) >= 0.0f;      // v_th = 1
            bool sk = (hk - 1.0f) >= 0.0f;
            vq = sq ? 0.f : hq;                 // hard reset
            vk = sk ? 0.f : hk;
            if (sq) qs[t] += 1.0f;
            if (sk) kb[t] |= (1ull << d);
        }
    }

    // attention LIF over the per-head spike-count (exact small integers)
    float va = 0.f;
#pragma unroll
    for (int t = 0; t < 4; t++) {
        float h = va + (qs[t] - va) * 0.5f;
        bool s  = (h - 0.5f) >= 0.0f;           // v_th = 0.5
        va = s ? 0.f : h;
        unsigned long long kbt = s ? kb[t] : 0ull;
        int ob = t * BCHW + base0;
        for (int d = 0; d < DH; d++)
            g_y[ob + d * HW] = ((kbt >> d) & 1ull) ? 1.0f : 0.0f;
    }
}

// ---------------------------------------------------------------------------
// Final LIF on the projected/BN'd activations -> output spikes
// ---------------------------------------------------------------------------
__global__ void lif_out_kernel(float* __restrict__ out)
{
    int idx = blockIdx.x * blockDim.x + threadIdx.x;
    if (idx >= BCHW) return;
    float v = 0.f;
#pragma unroll
    for (int t = 0; t < 4; t++) {
        float x = g_zbn[idx + t * BCHW];
        float h = v + (x - v) * 0.5f;
        bool s  = (h - 1.0f) >= 0.0f;
        v = s ? 0.f : h;
        out[idx + t * BCHW] = s ? 1.0f : 0.0f;
    }
}

// ---------------------------------------------------------------------------
extern "C" void kernel_launch(void* const* d_in, const int* in_sizes, int n_in,
                              void* d_out, int out_size)
{
    const float* x          = (const float*)d_in[0];
    const float* q_w        = (const float*)d_in[1];
    const float* q_gamma    = (const float*)d_in[2];
    const float* q_beta     = (const float*)d_in[3];
    const float* q_mean     = (const float*)d_in[4];
    const float* q_var      = (const float*)d_in[5];
    const float* k_w        = (const float*)d_in[6];
    const float* k_gamma    = (const float*)d_in[7];
    const float* k_beta     = (const float*)d_in[8];
    const float* k_mean     = (const float*)d_in[9];
    const float* k_var      = (const float*)d_in[10];
    const float* proj_w     = (const float*)d_in[11];
    const float* proj_b     = (const float*)d_in[12];
    const float* proj_gamma = (const float*)d_in[13];
    const float* proj_beta  = (const float*)d_in[14];
    const float* proj_mean  = (const float*)d_in[15];
    const float* proj_var   = (const float*)d_in[16];

    dim3 ggrid(NTOT / 128, CH / 128);   // (196, 3)

    gemm_q_kernel<<<ggrid, 256>>>(x, q_w, q_gamma, q_beta, q_mean, q_var);
    gemm_k_kernel<<<ggrid, 256>>>(x, k_w, k_gamma, k_beta, k_mean, k_var);
    lif_attn_kernel<<<BATCH * HEADS, 224>>>();
    gemm_proj_kernel<<<ggrid, 256>>>(proj_w, proj_gamma, proj_beta,
                                     proj_mean, proj_var, proj_b);
    lif_out_kernel<<<(BCHW + 255) / 256, 256>>>((float*)d_out);
}

// round 3
// speedup vs baseline: 1.1802x; 1.1802x over previous
#include <cuda_runtime.h>

// Problem constants
#define T_STEPS 4
#define BATCH   32
#define CH      384
#define HW      196
#define HEADS   8
#define DH      48
#define CHW     (CH*HW)          // 75264
#define BCHW    (BATCH*CHW)      // 2408448
#define TOTAL   (T_STEPS*BCHW)   // 9633792
#define NTOT    (T_STEPS*BATCH*HW) // 25088  (= 196 * 128 exactly)
#define NCHUNK  (CH/8)           // 48 k-chunks

// Scratch (static device globals -- allocation-guard safe)
__device__ float g_qbn[TOTAL];
__device__ float g_kbn[TOTAL];
__device__ float g_y[TOTAL];
__device__ float g_zbn[TOTAL];

// ---------------------------------------------------------------------------
// SGEMM 128x128x8, 256 threads, 8x8 microtile, fused BN epilogue.
// Double-buffered smem (2 stages), ONE __syncthreads per 8-k chunk, global
// prefetch overlapped with the FFMA block. Buffer parity resolved statically
// via manual 2x unroll. All tile dims divide exactly: no masking anywhere.
// ---------------------------------------------------------------------------
__device__ __forceinline__ void gemm_bn_body(
    const float* __restrict__ X, const float* __restrict__ W,
    const float* __restrict__ gamma, const float* __restrict__ beta,
    const float* __restrict__ mean,  const float* __restrict__ var,
    const float* __restrict__ bias,  float* __restrict__ out)
{
    __shared__ float As[2][8][128];   // [stage][k][m]
    __shared__ float Bs[2][8][128];   // [stage][k][n]
    __shared__ int   colOff[128];

    const int tid   = threadIdx.x;
    const int mbase = blockIdx.y * 128;
    const int nbase = blockIdx.x * 128;

    if (tid < 128) {
        int n  = nbase + tid;
        int tb = n / HW;
        colOff[tid] = tb * CHW + (n - tb * HW);
    }
    __syncthreads();

    const int tx = tid & 15;     // n direction (16)
    const int ty = tid >> 4;     // m direction (16)

    // load mapping
    const int a_row = tid >> 1;        // 0..127
    const int a_col = (tid & 1) * 4;   // 0 or 4
    const int b_k   = tid >> 5;        // 0..7
    const int b_n   = (tid & 31) * 4;  // 0..124

    const int bo0 = colOff[b_n + 0];
    const int bo1 = colOff[b_n + 1];
    const int bo2 = colOff[b_n + 2];
    const int bo3 = colOff[b_n + 3];

    const float* wptr = &W[(mbase + a_row) * CH + a_col];

    float acc[8][8];
#pragma unroll
    for (int i = 0; i < 8; i++)
#pragma unroll
        for (int j = 0; j < 8; j++) acc[i][j] = 0.f;

    // --- preload chunk 0 into stage 0 ---
    {
        float4 av = *reinterpret_cast<const float4*>(wptr);
        const int krow = b_k * HW;
        As[0][a_col + 0][a_row] = av.x;
        As[0][a_col + 1][a_row] = av.y;
        As[0][a_col + 2][a_row] = av.z;
        As[0][a_col + 3][a_row] = av.w;
        *reinterpret_cast<float4*>(&Bs[0][b_k][b_n]) =
            make_float4(X[bo0 + krow], X[bo1 + krow], X[bo2 + krow], X[bo3 + krow]);
    }
    __syncthreads();

#define COMPUTE_STAGE(S)                                                        \
    _Pragma("unroll")                                                           \
    for (int k = 0; k < 8; k++) {                                               \
        float4 A0 = *reinterpret_cast<const float4*>(&As[S][k][ty * 4]);        \
        float4 A1 = *reinterpret_cast<const float4*>(&As[S][k][64 + ty * 4]);   \
        float4 B0 = *reinterpret_cast<const float4*>(&Bs[S][k][tx * 4]);        \
        float4 B1 = *reinterpret_cast<const float4*>(&Bs[S][k][64 + tx * 4]);   \
        float ar[8] = {A0.x, A0.y, A0.z, A0.w, A1.x, A1.y, A1.z, A1.w};         \
        float br[8] = {B0.x, B0.y, B0.z, B0.w, B1.x, B1.y, B1.z, B1.w};         \
        _Pragma("unroll")                                                       \
        for (int i = 0; i < 8; i++)                                             \
            _Pragma("unroll")                                                   \
            for (int j = 0; j < 8; j++)                                         \
                acc[i][j] = fmaf(ar[i], br[j], acc[i][j]);                      \
    }

#pragma unroll 1
    for (int it = 0; it < NCHUNK; it += 2) {
        // -- stage 0 compute, prefetch chunk it+1 -> stage 1 (always valid) --
        {
            float4 av = *reinterpret_cast<const float4*>(wptr + (it + 1) * 8);
            const int krow = ((it + 1) * 8 + b_k) * HW;
            float x0 = X[bo0 + krow];
            float x1 = X[bo1 + krow];
            float x2 = X[bo2 + krow];
            float x3 = X[bo3 + krow];

            COMPUTE_STAGE(0)

            As[1][a_col + 0][a_row] = av.x;
            As[1][a_col + 1][a_row] = av.y;
            As[1][a_col + 2][a_row] = av.z;
            As[1][a_col + 3][a_row] = av.w;
            *reinterpret_cast<float4*>(&Bs[1][b_k][b_n]) = make_float4(x0, x1, x2, x3);
            __syncthreads();
        }
        // -- stage 1 compute, prefetch chunk it+2 -> stage 0 (except last) --
        if (it + 2 < NCHUNK) {
            float4 av = *reinterpret_cast<const float4*>(wptr + (it + 2) * 8);
            const int krow = ((it + 2) * 8 + b_k) * HW;
            float x0 = X[bo0 + krow];
            float x1 = X[bo1 + krow];
            float x2 = X[bo2 + krow];
            float x3 = X[bo3 + krow];

            COMPUTE_STAGE(1)

            As[0][a_col + 0][a_row] = av.x;
            As[0][a_col + 1][a_row] = av.y;
            As[0][a_col + 2][a_row] = av.z;
            As[0][a_col + 3][a_row] = av.w;
            *reinterpret_cast<float4*>(&Bs[0][b_k][b_n]) = make_float4(x0, x1, x2, x3);
            __syncthreads();
        } else {
            COMPUTE_STAGE(1)
        }
    }
#undef COMPUTE_STAGE

    // BN (+optional conv bias) epilogue, matching reference op order exactly
#pragma unroll
    for (int i = 0; i < 8; i++) {
        int m = (i < 4) ? (ty * 4 + i) : (64 + ty * 4 + (i - 4));
        int o = mbase + m;
        float inv = gamma[o] / sqrtf(var[o] + 1e-5f);
        float sh  = beta[o] - mean[o] * inv;
        float bv  = bias ? bias[o] : 0.f;
#pragma unroll
        for (int j = 0; j < 8; j++) {
            int n = (j < 4) ? (tx * 4 + j) : (64 + tx * 4 + (j - 4));
            float v = acc[i][j] + bv;
            out[colOff[n] + o * HW] = v * inv + sh;
        }
    }
}

__global__ void __launch_bounds__(256, 2) gemm_q_kernel(
    const float* __restrict__ X, const float* __restrict__ W,
    const float* __restrict__ g, const float* __restrict__ b,
    const float* __restrict__ m, const float* __restrict__ v)
{
    gemm_bn_body(X, W, g, b, m, v, nullptr, g_qbn);
}

__global__ void __launch_bounds__(256, 2) gemm_k_kernel(
    const float* __restrict__ X, const float* __restrict__ W,
    const float* __restrict__ g, const float* __restrict__ b,
    const float* __restrict__ m, const float* __restrict__ v)
{
    gemm_bn_body(X, W, g, b, m, v, nullptr, g_kbn);
}

__global__ void __launch_bounds__(256, 2) gemm_proj_kernel(
    const float* __restrict__ W,
    const float* __restrict__ g, const float* __restrict__ b,
    const float* __restrict__ m, const float* __restrict__ v,
    const float* __restrict__ bias)
{
    gemm_bn_body(g_y, W, g, b, m, v, bias, g_zbn);
}

// ---------------------------------------------------------------------------
// LIF on q and k (per channel, over T), per-head sum-pool, attn LIF (vth=0.5),
// gate k spikes -> binary y.  One CTA per (b, head); one thread per hw.
// ---------------------------------------------------------------------------
__global__ void lif_attn_kernel()
{
    int bh   = blockIdx.x;
    int b    = bh >> 3;
    int head = bh & 7;
    int hw   = threadIdx.x;
    if (hw >= HW) return;

    int cbase = head * DH;
    int base0 = b * CHW + cbase * HW + hw;

    float qs[4] = {0.f, 0.f, 0.f, 0.f};
    unsigned long long kb[4] = {0ull, 0ull, 0ull, 0ull};

    for (int d = 0; d < DH; d++) {
        int idx = base0 + d * HW;
        float vq = 0.f, vk = 0.f;
#pragma unroll
        for (int t = 0; t < 4; t++) {
            float xq = g_qbn[idx + t * BCHW];
            float xk = g_kbn[idx + t * BCHW];
            float hq = vq + (xq - vq) * 0.5f;   // tau = 2
            float hk = vk + (xk - vk) * 0.5f;
            bool sq = (hq - 1.0f) >= 0.0f;      // v_th = 1
            bool sk = (hk - 1.0f) >= 0.0f;
            vq = sq ? 0.f : hq;                 // hard reset
            vk = sk ? 0.f : hk;
            if (sq) qs[t] += 1.0f;
            if (sk) kb[t] |= (1ull << d);
        }
    }

    // attention LIF over the per-head spike-count (exact small integers)
    float va = 0.f;
#pragma unroll
    for (int t = 0; t < 4; t++) {
        float h = va + (qs[t] - va) * 0.5f;
        bool s  = (h - 0.5f) >= 0.0f;           // v_th = 0.5
        va = s ? 0.f : h;
        unsigned long long kbt = s ? kb[t] : 0ull;
        int ob = t * BCHW + base0;
        for (int d = 0; d < DH; d++)
            g_y[ob + d * HW] = ((kbt >> d) & 1ull) ? 1.0f : 0.0f;
    }
}

// ---------------------------------------------------------------------------
// Final LIF on the projected/BN'd activations -> output spikes
// ---------------------------------------------------------------------------
__global__ void lif_out_kernel(float* __restrict__ out)
{
    int idx = blockIdx.x * blockDim.x + threadIdx.x;
    if (idx >= BCHW) return;
    float v = 0.f;
#pragma unroll
    for (int t = 0; t < 4; t++) {
        float x = g_zbn[idx + t * BCHW];
        float h = v + (x - v) * 0.5f;
        bool s  = (h - 1.0f) >= 0.0f;
        v = s ? 0.f : h;
        out[idx + t * BCHW] = s ? 1.0f : 0.0f;
    }
}

// ---------------------------------------------------------------------------
extern "C" void kernel_launch(void* const* d_in, const int* in_sizes, int n_in,
                              void* d_out, int out_size)
{
    const float* x          = (const float*)d_in[0];
    const float* q_w        = (const float*)d_in[1];
    const float* q_gamma    = (const float*)d_in[2];
    const float* q_beta     = (const float*)d_in[3];
    const float* q_mean     = (const float*)d_in[4];
    const float* q_var      = (const float*)d_in[5];
    const float* k_w        = (const float*)d_in[6];
    const float* k_gamma    = (const float*)d_in[7];
    const float* k_beta     = (const float*)d_in[8];
    const float* k_mean     = (const float*)d_in[9];
    const float* k_var      = (const float*)d_in[10];
    const float* proj_w     = (const float*)d_in[11];
    const float* proj_b     = (const float*)d_in[12];
    const float* proj_gamma = (const float*)d_in[13];
    const float* proj_beta  = (const float*)d_in[14];
    const float* proj_mean  = (const float*)d_in[15];
    const float* proj_var   = (const float*)d_in[16];

    dim3 ggrid(NTOT / 128, CH / 128);   // (196, 3)

    gemm_q_kernel<<<ggrid, 256>>>(x, q_w, q_gamma, q_beta, q_mean, q_var);
    gemm_k_kernel<<<ggrid, 256>>>(x, k_w, k_gamma, k_beta, k_mean, k_var);
    lif_attn_kernel<<<BATCH * HEADS, 224>>>();
    gemm_proj_kernel<<<ggrid, 256>>>(proj_w, proj_gamma, proj_beta,
                                     proj_mean, proj_var, proj_b);
    lif_out_kernel<<<(BCHW + 255) / 256, 256>>>((float*)d_out);
}